// round 17
// baseline (speedup 1.0000x reference)
#include <cuda_runtime.h>
#include <cstdint>

#define NN 100000
#define E0 1600000
#define ET (E0 + NN)
#define NEG_SLOPE 0.2f

// ---------------- scratch (__device__ globals, no allocation) ----------------
static __device__ __align__(16) float g_h1[NN * 64];           // layer1 pre-agg features
static __device__ __align__(16) float g_hh[NN * 64];           // layer1 output (post ELU)
static __device__ __align__(16) float g_agg[(size_t)NN * 512]; // layer2 aggregated hh per head
static __device__ __align__(16) float g_as1[NN * 8];
static __device__ __align__(16) float g_ad1[NN * 8];
static __device__ __align__(16) float g_as2[NN * 8];
static __device__ __align__(16) float g_ad2[NN * 8];
static __device__ __align__(16) float g_wts[512];    // w~_src[h*64+k]
static __device__ __align__(16) float g_wtd[512];    // w~_dst[h*64+k]
static __device__ __align__(16) float g_wfold[512 * 64]; // Wfold[h*64+k][f] = W2[k][h*64+f]
static __device__ int   g_src[ET];
static __device__ int   g_dst[ET];
static __device__ int   g_deg[NN];
static __device__ int   g_cur[NN];
static __device__ int   g_off[NN + 1];
static __device__ int   g_csr_src[ET];
static __device__ int   g_top[128];
static __device__ int   g_edge_is64;

// ---------------- edge dtype sniff: int64 (value,0 pairs) vs int32 ----------------
__global__ void detect_edge_fmt_kernel(const int* __restrict__ e32) {
    if (blockIdx.x == 0 && threadIdx.x == 0) {
        int is64 = 1;
        for (int i = 0; i < 256; i++) {
            if (e32[2 * i + 1] != 0) { is64 = 0; break; }
        }
        g_edge_is64 = is64;
    }
}

// ---------------- init: zero degree/cursor ----------------
__global__ void init_kernel() {
    int i = blockIdx.x * blockDim.x + threadIdx.x;
    if (i < NN) { g_deg[i] = 0; g_cur[i] = 0; }
}

// ---------------- edge prep: decode + self loops + degree histogram ----------------
__global__ void prep_edges_kernel(const int* __restrict__ e32) {
    int i = blockIdx.x * blockDim.x + threadIdx.x;
    if (i >= ET) return;
    int s, d;
    if (i < E0) {
        if (g_edge_is64) {
            s = e32[2 * (size_t)i];
            d = e32[2 * ((size_t)E0 + i)];
        } else {
            s = e32[i];
            d = e32[(size_t)E0 + i];
        }
    } else {
        s = i - E0; d = i - E0;
    }
    g_src[i] = s;
    g_dst[i] = d;
    atomicAdd(&g_deg[d], 1);
}

// ---------------- prefix scan of degrees -> g_off ----------------
__global__ __launch_bounds__(1024) void scan_blocks_kernel() {
    __shared__ int ws[32];
    int i = blockIdx.x * 1024 + threadIdx.x;
    int lane = threadIdx.x & 31, wid = threadIdx.x >> 5;
    int v = (i < NN) ? g_deg[i] : 0;
    int x = v;
#pragma unroll
    for (int o = 1; o < 32; o <<= 1) {
        int y = __shfl_up_sync(0xffffffffu, x, o);
        if (lane >= o) x += y;
    }
    if (lane == 31) ws[wid] = x;
    __syncthreads();
    if (threadIdx.x < 32) {
        int s = ws[threadIdx.x];
#pragma unroll
        for (int o = 1; o < 32; o <<= 1) {
            int y = __shfl_up_sync(0xffffffffu, s, o);
            if ((int)threadIdx.x >= o) s += y;
        }
        ws[threadIdx.x] = s;
    }
    __syncthreads();
    int base = (wid > 0) ? ws[wid - 1] : 0;
    if (i < NN) g_off[i] = base + x - v;
    if (threadIdx.x == 0) g_top[blockIdx.x] = ws[31];
}

__global__ void scan_tops_kernel(int nb) {
    if (threadIdx.x == 0 && blockIdx.x == 0) {
        int run = 0;
        for (int b = 0; b < nb; b++) { int t = g_top[b]; g_top[b] = run; run += t; }
    }
}

__global__ __launch_bounds__(1024) void scan_add_kernel() {
    int i = blockIdx.x * 1024 + threadIdx.x;
    if (i < NN) g_off[i] += g_top[blockIdx.x];
    if (i == 0) g_off[NN] = ET;
}

// ---------------- scatter edges into CSR (by dst) ----------------
__global__ void scatter_kernel() {
    int i = blockIdx.x * blockDim.x + threadIdx.x;
    if (i >= ET) return;
    int d = g_dst[i];
    int pos = g_off[d] + atomicAdd(&g_cur[d], 1);
    g_csr_src[pos] = g_src[i];
}

// ---------------- precompute: Wfold + w~ vectors ----------------
__global__ void prep_w2_kernel(const float* __restrict__ W2,
                               const float* __restrict__ a_s2,
                               const float* __restrict__ a_d2) {
    int i = blockIdx.x * blockDim.x + threadIdx.x;  // 0..32767
    if (i < 512 * 64) {
        int r = i >> 6, f = i & 63;
        int h = r >> 6, k = r & 63;
        g_wfold[i] = W2[k * 512 + h * 64 + f];
    }
    if (i < 512) {
        int h = i >> 6, k = i & 63;
        float ss = 0.0f, dd = 0.0f;
        const float* wrow = W2 + k * 512 + h * 64;
#pragma unroll 8
        for (int f = 0; f < 64; f++) {
            float w = wrow[f];
            ss += w * a_s2[h * 64 + f];
            dd += w * a_d2[h * 64 + f];
        }
        g_wts[i] = ss;
        g_wtd[i] = dd;
    }
}

// ---------------- TF32 helpers ----------------
__device__ __forceinline__ float to_tf32(float f) {
    uint32_t u;
    asm("cvt.rna.tf32.f32 %0, %1;" : "=r"(u) : "f"(f));
    return __uint_as_float(u);
}
__device__ __forceinline__ float4 to_tf32_4(float4 v) {
    return make_float4(to_tf32(v.x), to_tf32(v.y), to_tf32(v.z), to_tf32(v.w));
}

// ---------------- TF32 tensor-core GEMM: C[N,64] = A[N,KTOT] @ W[KTOT,64] (+bias) ----
// MODE 0: A=x, W=W1, C=g_h1; fused alphas1 (per-head dots with a_src1/a_dst1) in epilogue.
// MODE 1: A=g_agg, W=g_wfold, C=out, +bias b2.
template <int KTOT, int MODE>
__global__ __launch_bounds__(256) void gemm_tf32_kernel(
    const float* __restrict__ Ap, const float* __restrict__ Wp,
    float* __restrict__ Cp, const float* __restrict__ biasp,
    const float* __restrict__ asrcp, const float* __restrict__ adstp)
{
    const float* A = (MODE == 0) ? Ap : g_agg;
    const float* W = (MODE == 0) ? Wp : g_wfold;
    float* C = (MODE == 0) ? g_h1 : Cp;

    __shared__ __align__(16) float xs[128 * 36];  // [row][k] stride 36
    __shared__ __align__(16) float wsm[32 * 72];  // [k][col] stride 72
    __shared__ float sa[64], sdv[64];
    const int NCH = KTOT / 32;

    int tid = threadIdx.x;
    int wid = tid >> 5, lane = tid & 31;
    int gid = lane >> 2, tig = lane & 3;
    int row0 = blockIdx.x * 128;
    int warp_r0 = wid * 16;

    int lr = tid >> 3;
    int k4 = (tid & 7) << 2;
    int wk0 = tid >> 4;
    int wc4 = (tid & 15) << 2;

    if (MODE == 0) {
        if (tid < 64) sa[tid] = asrcp[tid];
        else if (tid < 128) sdv[tid - 64] = adstp[tid - 64];
    }

    size_t arow[4];
#pragma unroll
    for (int i = 0; i < 4; i++) {
        int r = row0 + lr + 32 * i;
        arow[i] = (size_t)(r < NN ? r : NN - 1) * KTOT;
    }

    float4 xa[4], wa[2];
#pragma unroll
    for (int i = 0; i < 4; i++)
        xa[i] = *(const float4*)(A + arow[i] + k4);
    wa[0] = ((const float4*)W)[tid];
    wa[1] = ((const float4*)W)[tid + 256];
#pragma unroll
    for (int i = 0; i < 4; i++)
        *(float4*)(xs + (lr + 32 * i) * 36 + k4) = to_tf32_4(xa[i]);
    *(float4*)(wsm + wk0 * 72 + wc4) = to_tf32_4(wa[0]);
    *(float4*)(wsm + (wk0 + 16) * 72 + wc4) = to_tf32_4(wa[1]);
    __syncthreads();

    float acc[8][4] = {};
    const uint32_t* xsu = (const uint32_t*)xs;
    const uint32_t* wsu = (const uint32_t*)wsm;

    for (int c = 0; c < NCH; c++) {
        if (c + 1 < NCH) {
            int ko = (c + 1) * 32;
#pragma unroll
            for (int i = 0; i < 4; i++)
                xa[i] = *(const float4*)(A + arow[i] + ko + k4);
            wa[0] = ((const float4*)(W + ko * 64))[tid];
            wa[1] = ((const float4*)(W + ko * 64))[tid + 256];
        }
#pragma unroll
        for (int kk = 0; kk < 4; kk++) {
            int k8 = kk * 8;
            uint32_t a0 = xsu[(warp_r0 + gid) * 36 + k8 + tig];
            uint32_t a1 = xsu[(warp_r0 + gid + 8) * 36 + k8 + tig];
            uint32_t a2 = xsu[(warp_r0 + gid) * 36 + k8 + tig + 4];
            uint32_t a3 = xsu[(warp_r0 + gid + 8) * 36 + k8 + tig + 4];
#pragma unroll
            for (int t = 0; t < 8; t++) {
                uint32_t b0 = wsu[(k8 + tig) * 72 + t * 8 + gid];
                uint32_t b1 = wsu[(k8 + tig + 4) * 72 + t * 8 + gid];
                asm volatile(
                    "mma.sync.aligned.m16n8k8.row.col.f32.tf32.tf32.f32 "
                    "{%0,%1,%2,%3}, {%4,%5,%6,%7}, {%8,%9}, {%0,%1,%2,%3};"
                    : "+f"(acc[t][0]), "+f"(acc[t][1]), "+f"(acc[t][2]), "+f"(acc[t][3])
                    : "r"(a0), "r"(a1), "r"(a2), "r"(a3), "r"(b0), "r"(b1));
            }
        }
        if (c + 1 < NCH) {
            __syncthreads();
#pragma unroll
            for (int i = 0; i < 4; i++)
                *(float4*)(xs + (lr + 32 * i) * 36 + k4) = to_tf32_4(xa[i]);
            *(float4*)(wsm + wk0 * 72 + wc4) = to_tf32_4(wa[0]);
            *(float4*)(wsm + (wk0 + 16) * 72 + wc4) = to_tf32_4(wa[1]);
            __syncthreads();
        }
    }

    int r = row0 + warp_r0 + gid;
    float as_lo[8], ad_lo[8], as_hi[8], ad_hi[8];
#pragma unroll
    for (int t = 0; t < 8; t++) {
        int col = t * 8 + 2 * tig;
        float bx = 0.0f, by = 0.0f;
        if (MODE == 1) { bx = biasp[col]; by = biasp[col + 1]; }
        if (r < NN) {
            float2 v = make_float2(acc[t][0] + bx, acc[t][1] + by);
            *(float2*)(C + (size_t)r * 64 + col) = v;
        }
        if (r + 8 < NN) {
            float2 v = make_float2(acc[t][2] + bx, acc[t][3] + by);
            *(float2*)(C + (size_t)(r + 8) * 64 + col) = v;
        }
        if (MODE == 0) {
            // alphas1: head of col t*8+2tig is t; partial dot over this lane's 2 cols
            as_lo[t] = acc[t][0] * sa[col] + acc[t][1] * sa[col + 1];
            ad_lo[t] = acc[t][0] * sdv[col] + acc[t][1] * sdv[col + 1];
            as_hi[t] = acc[t][2] * sa[col] + acc[t][3] * sa[col + 1];
            ad_hi[t] = acc[t][2] * sdv[col] + acc[t][3] * sdv[col + 1];
        }
    }
    if (MODE == 0) {
#pragma unroll
        for (int t = 0; t < 8; t++) {
#pragma unroll
            for (int o = 1; o <= 2; o <<= 1) {
                as_lo[t] += __shfl_xor_sync(0xffffffffu, as_lo[t], o);
                ad_lo[t] += __shfl_xor_sync(0xffffffffu, ad_lo[t], o);
                as_hi[t] += __shfl_xor_sync(0xffffffffu, as_hi[t], o);
                ad_hi[t] += __shfl_xor_sync(0xffffffffu, ad_hi[t], o);
            }
        }
        if (tig == 0) {
            if (r < NN) {
                *(float4*)(g_as1 + (size_t)r * 8)     = make_float4(as_lo[0], as_lo[1], as_lo[2], as_lo[3]);
                *(float4*)(g_as1 + (size_t)r * 8 + 4) = make_float4(as_lo[4], as_lo[5], as_lo[6], as_lo[7]);
                *(float4*)(g_ad1 + (size_t)r * 8)     = make_float4(ad_lo[0], ad_lo[1], ad_lo[2], ad_lo[3]);
                *(float4*)(g_ad1 + (size_t)r * 8 + 4) = make_float4(ad_lo[4], ad_lo[5], ad_lo[6], ad_lo[7]);
            }
            if (r + 8 < NN) {
                *(float4*)(g_as1 + (size_t)(r + 8) * 8)     = make_float4(as_hi[0], as_hi[1], as_hi[2], as_hi[3]);
                *(float4*)(g_as1 + (size_t)(r + 8) * 8 + 4) = make_float4(as_hi[4], as_hi[5], as_hi[6], as_hi[7]);
                *(float4*)(g_ad1 + (size_t)(r + 8) * 8)     = make_float4(ad_hi[0], ad_hi[1], ad_hi[2], ad_hi[3]);
                *(float4*)(g_ad1 + (size_t)(r + 8) * 8 + 4) = make_float4(ad_hi[4], ad_hi[5], ad_hi[6], ad_hi[7]);
            }
        }
    }
}

// ---------------- FUSED softmax+aggregation: warp per dst node, single edge pass ----
// L==0: feat=g_h1 -> g_hh (fused /den+bias+ELU) + fused alphas2 (w~ dots) epilogue
// L==1: feat=g_hh -> g_agg (fused *0.125/den)
// 4-edge software-pipelined gather (MLP 8) in the inner loop.
template <int L>
__global__ __launch_bounds__(256) void agg_fused_kernel(const float* __restrict__ b1) {
    __shared__ __align__(16) float ps[256 * 8];   // [warp][32 edges][8 heads]
    __shared__ float ss[512], sd[512];            // w~ tables (L==0 only)
    const float* as = (L == 0) ? g_as1 : g_as2;
    const float* ad = (L == 0) ? g_ad1 : g_ad2;
    const float* feat = (L == 0) ? g_h1 : g_hh;
    int lane = threadIdx.x & 31;
    int wid = (threadIdx.x >> 5) & 7;
    int n = (blockIdx.x * blockDim.x + threadIdx.x) >> 5;

    if (L == 0) {
        for (int i = threadIdx.x; i < 512; i += 256) { ss[i] = g_wts[i]; sd[i] = g_wtd[i]; }
        __syncthreads();
    }
    if (n >= NN) return;
    int beg = g_off[n], end = g_off[n + 1];

    float4 adv0 = *(const float4*)(ad + (size_t)n * 8);
    float4 adv1 = *(const float4*)(ad + (size_t)n * 8 + 4);

    float den[8] = {};
    float a0 = 0.0f, a1 = 0.0f;   // L==0 accumulators
    float acc[16] = {};           // L==1 accumulators

    float* myps = ps + (wid * 32 + lane) * 8;
    const float* wp = ps + wid * 256;
    int h0 = lane >> 3;

    for (int chunk = beg; chunk < end; chunk += 32) {
        int idx = chunk + lane;
        bool valid = idx < end;
        int myS = valid ? g_csr_src[idx] : 0;
        float p[8];
        if (valid) {
            float4 s0 = *(const float4*)(as + (size_t)myS * 8);
            float4 s1 = *(const float4*)(as + (size_t)myS * 8 + 4);
            float e[8] = {s0.x + adv0.x, s0.y + adv0.y, s0.z + adv0.z, s0.w + adv0.w,
                          s1.x + adv1.x, s1.y + adv1.y, s1.z + adv1.z, s1.w + adv1.w};
#pragma unroll
            for (int h = 0; h < 8; h++) {
                float ev = e[h];
                ev = (ev > 0.0f) ? ev : NEG_SLOPE * ev;
                p[h] = __expf(ev);
                den[h] += p[h];
            }
        } else {
#pragma unroll
            for (int h = 0; h < 8; h++) p[h] = 0.0f;
        }
        *(float4*)myps       = make_float4(p[0], p[1], p[2], p[3]);
        *(float4*)(myps + 4) = make_float4(p[4], p[5], p[6], p[7]);
        __syncwarp();

        int cnt = min(32, end - chunk);
        int j = 0;
        // 4-edge pipelined gather: 8 independent LDGs in flight
        for (; j + 4 <= cnt; j += 4) {
            int s0 = __shfl_sync(0xffffffffu, myS, j);
            int s1 = __shfl_sync(0xffffffffu, myS, j + 1);
            int s2 = __shfl_sync(0xffffffffu, myS, j + 2);
            int s3 = __shfl_sync(0xffffffffu, myS, j + 3);
            const float* f0 = feat + (size_t)s0 * 64;
            const float* f1 = feat + (size_t)s1 * 64;
            const float* f2 = feat + (size_t)s2 * 64;
            const float* f3 = feat + (size_t)s3 * 64;
            float x00 = f0[lane], x01 = f0[32 + lane];
            float x10 = f1[lane], x11 = f1[32 + lane];
            float x20 = f2[lane], x21 = f2[32 + lane];
            float x30 = f3[lane], x31 = f3[32 + lane];
            if (L == 0) {
                a0 += wp[(j + 0) * 8 + h0] * x00;  a1 += wp[(j + 0) * 8 + 4 + h0] * x01;
                a0 += wp[(j + 1) * 8 + h0] * x10;  a1 += wp[(j + 1) * 8 + 4 + h0] * x11;
                a0 += wp[(j + 2) * 8 + h0] * x20;  a1 += wp[(j + 2) * 8 + 4 + h0] * x21;
                a0 += wp[(j + 3) * 8 + h0] * x30;  a1 += wp[(j + 3) * 8 + 4 + h0] * x31;
            } else {
#pragma unroll
                for (int q = 0; q < 4; q++) {
                    float xv0 = (q == 0) ? x00 : (q == 1) ? x10 : (q == 2) ? x20 : x30;
                    float xv1 = (q == 0) ? x01 : (q == 1) ? x11 : (q == 2) ? x21 : x31;
                    float4 p0 = *(const float4*)(wp + (j + q) * 8);
                    float4 p1 = *(const float4*)(wp + (j + q) * 8 + 4);
                    acc[0] += p0.x * xv0;  acc[8]  += p0.x * xv1;
                    acc[1] += p0.y * xv0;  acc[9]  += p0.y * xv1;
                    acc[2] += p0.z * xv0;  acc[10] += p0.z * xv1;
                    acc[3] += p0.w * xv0;  acc[11] += p0.w * xv1;
                    acc[4] += p1.x * xv0;  acc[12] += p1.x * xv1;
                    acc[5] += p1.y * xv0;  acc[13] += p1.y * xv1;
                    acc[6] += p1.z * xv0;  acc[14] += p1.z * xv1;
                    acc[7] += p1.w * xv0;  acc[15] += p1.w * xv1;
                }
            }
        }
        for (; j < cnt; j++) {
            int s = __shfl_sync(0xffffffffu, myS, j);
            float hv0 = feat[(size_t)s * 64 + lane];
            float hv1 = feat[(size_t)s * 64 + 32 + lane];
            if (L == 0) {
                a0 += wp[j * 8 + h0] * hv0;
                a1 += wp[j * 8 + 4 + h0] * hv1;
            } else {
                float4 p0 = *(const float4*)(wp + j * 8);
                float4 p1 = *(const float4*)(wp + j * 8 + 4);
                acc[0] += p0.x * hv0;  acc[8]  += p0.x * hv1;
                acc[1] += p0.y * hv0;  acc[9]  += p0.y * hv1;
                acc[2] += p0.z * hv0;  acc[10] += p0.z * hv1;
                acc[3] += p0.w * hv0;  acc[11] += p0.w * hv1;
                acc[4] += p1.x * hv0;  acc[12] += p1.x * hv1;
                acc[5] += p1.y * hv0;  acc[13] += p1.y * hv1;
                acc[6] += p1.z * hv0;  acc[14] += p1.z * hv1;
                acc[7] += p1.w * hv0;  acc[15] += p1.w * hv1;
            }
        }
        __syncwarp();
    }

#pragma unroll
    for (int h = 0; h < 8; h++) {
#pragma unroll
        for (int o = 16; o >= 1; o >>= 1)
            den[h] += __shfl_xor_sync(0xffffffffu, den[h], o);
    }

    if (L == 0) {
        float d0 = (h0 < 2) ? (h0 == 0 ? den[0] : den[1]) : (h0 == 2 ? den[2] : den[3]);
        float d1 = (h0 < 2) ? (h0 == 0 ? den[4] : den[5]) : (h0 == 2 ? den[6] : den[7]);
        float v0 = a0 / d0 + b1[lane];
        float v1 = a1 / d1 + b1[32 + lane];
        v0 = (v0 > 0.0f) ? v0 : (__expf(v0) - 1.0f);
        v1 = (v1 > 0.0f) ? v1 : (__expf(v1) - 1.0f);
        g_hh[(size_t)n * 64 + lane]      = v0;
        g_hh[(size_t)n * 64 + 32 + lane] = v1;
        // fused alphas2: as2/ad2 dots against w~ tables, full-warp reductions
#pragma unroll
        for (int h = 0; h < 8; h++) {
            float a = v0 * ss[h * 64 + lane] + v1 * ss[h * 64 + 32 + lane];
            float b = v0 * sd[h * 64 + lane] + v1 * sd[h * 64 + 32 + lane];
#pragma unroll
            for (int o = 16; o >= 1; o >>= 1) {
                a += __shfl_xor_sync(0xffffffffu, a, o);
                b += __shfl_xor_sync(0xffffffffu, b, o);
            }
            if (lane == 0) {
                g_as2[n * 8 + h] = a;
                g_ad2[n * 8 + h] = b;
            }
        }
    } else {
#pragma unroll
        for (int h = 0; h < 8; h++) {
            float rd = 0.125f / den[h];
            g_agg[(size_t)n * 512 + h * 64 + lane]      = acc[h] * rd;
            g_agg[(size_t)n * 512 + h * 64 + 32 + lane] = acc[8 + h] * rd;
        }
    }
}

// ---------------- launch ----------------
extern "C" void kernel_launch(void* const* d_in, const int* in_sizes, int n_in,
                              void* d_out, int out_size) {
    const float *x = 0, *W1 = 0, *W2 = 0, *a_src1 = 0, *a_dst1 = 0, *b1 = 0;
    const float *a_src2 = 0, *a_dst2 = 0, *b2 = 0;
    const void* edge = 0;
    int n64 = 0, n512 = 0;
    for (int i = 0; i < n_in; i++) {
        int sz = in_sizes[i];
        const float* p = (const float*)d_in[i];
        if (sz == 25600000) x = p;
        else if (sz == 16384) W1 = p;
        else if (sz == 32768) W2 = p;
        else if (sz == 3200000) edge = d_in[i];
        else if (sz == 512) { if (n512 == 0) a_src2 = p; else a_dst2 = p; n512++; }
        else if (sz == 64) {
            if (n64 == 0) a_src1 = p;
            else if (n64 == 1) a_dst1 = p;
            else if (n64 == 2) b1 = p;
            else b2 = p;
            n64++;
        }
    }
    float* out = (float*)d_out;

    const int TPB = 256;
    int edge_blocks = (ET + TPB - 1) / TPB;
    int node_blocks = (NN + TPB - 1) / TPB;
    int warp_node_blocks = (NN * 32 + TPB - 1) / TPB;  // warp per node
    int scan_blocks = (NN + 1023) / 1024;              // 98
    int gemm_blocks = (NN + 127) / 128;                // 782

    // CSR build + weight precompute
    detect_edge_fmt_kernel<<<1, 32>>>((const int*)edge);
    init_kernel<<<node_blocks, TPB>>>();
    prep_edges_kernel<<<edge_blocks, TPB>>>((const int*)edge);
    scan_blocks_kernel<<<scan_blocks, 1024>>>();
    scan_tops_kernel<<<1, 32>>>(scan_blocks);
    scan_add_kernel<<<scan_blocks, 1024>>>();
    scatter_kernel<<<edge_blocks, TPB>>>();
    prep_w2_kernel<<<128, 256>>>(W2, a_src2, a_dst2);

    // Layer 1 (alphas1 fused into GEMM epilogue)
    gemm_tf32_kernel<256, 0><<<gemm_blocks, 256>>>(x, W1, 0, 0, a_src1, a_dst1);
    agg_fused_kernel<0><<<warp_node_blocks, TPB>>>(b1);   // + fused alphas2

    // Layer 2 (h2 never materialized)
    agg_fused_kernel<1><<<warp_node_blocks, TPB>>>(0);
    gemm_tf32_kernel<512, 1><<<gemm_blocks, 256>>>(0, 0, out, b2, 0, 0);
}